// round 16
// baseline (speedup 1.0000x reference)
#include <cuda_runtime.h>
#include <cuda_fp16.h>

// ---------------------------------------------------------------------------
// TPoseHuman fused 6-part MLP — layers 2 AND 3 on mma.sync fp16 (single-chain
// layer2 + layer3; validated rel_err 2.3e-4). R16 = R14 (TM=64, B direct from
// global in MMA-fragment layout, 2 CTAs/SM — the traffic-optimal config) +
// A-fragment DOUBLE BUFFERING: LDSM for half-stage hs+1 issues before the
// MMAs of hs, hiding shared-memory latency (R15 proved occupancy can't rise
// without raising traffic; this attacks the exposed LDSM latency instead).
// ---------------------------------------------------------------------------

#define NPTS    65536
#define PPARTS  6
#define TM      64
#define NCTAS   (NPTS / TM)       // 1024
#define THREADS 256
#define OUTC    27

// ---- smem byte offsets ----
#define OFF_AHI  0u               // 64 rows x 512B : layer1 A-hi plane
#define OFF_H2   32768u           // 64 rows x 512B : h2 fp16 plane (layer3 A)
#define SMEM_BYTES 65536

// ---------------------------------------------------------------------------
// asm helpers (baseline PTX, sm_80-era: family-safe on compute_103)
// ---------------------------------------------------------------------------
__device__ __forceinline__ unsigned smem_to_u32(const void* p) {
    unsigned a;
    asm("{ .reg .u64 t; cvta.to.shared.u64 t, %1; cvt.u32.u64 %0, t; }"
        : "=r"(a) : "l"(p));
    return a;
}
#define LDSM4(r, addr) \
    asm volatile("ldmatrix.sync.aligned.m8n8.x4.shared.b16 {%0,%1,%2,%3}, [%4];" \
        : "=r"((r)[0]), "=r"((r)[1]), "=r"((r)[2]), "=r"((r)[3]) : "r"(addr))
#define MMA16816(d, a, b0r, b1r) \
    asm volatile("mma.sync.aligned.m16n8k16.row.col.f32.f16.f16.f32 " \
        "{%0,%1,%2,%3}, {%4,%5,%6,%7}, {%8,%9}, {%0,%1,%2,%3};" \
        : "+f"((d)[0]), "+f"((d)[1]), "+f"((d)[2]), "+f"((d)[3]) \
        : "r"((a)[0]), "r"((a)[1]), "r"((a)[2]), "r"((a)[3]), \
          "r"(b0r), "r"(b1r))
__device__ __forceinline__ unsigned pack_h2(float x, float y) {
    __half2 t = __floats2half2_rn(x, y);
    return *(unsigned*)&t;
}
__device__ __forceinline__ unsigned pack_hh(__half x, __half y) {
    __half2 t = __halves2half2(x, y);
    return *(unsigned*)&t;
}

// ---------------------------------------------------------------------------
// persistent scratch — B operands in direct MMA-fragment layout
// ---------------------------------------------------------------------------
// g_B2: [p][wx(4)][hs(16)][t(4)][lane(32)] x uint4 — uniform 128-uint4 stride
__device__ __align__(16) uint4 g_B2[PPARTS * 4 * 16 * 4 * 32];      // 786KB
// g_B3: [p][nh(2)][ks(16)][lane(32)] x uint4 (hi split only)
__device__ __align__(16) uint4 g_B3[PPARTS * 2 * 16 * 32];          // 98KB
__device__ __align__(16) float g_W1r  [PPARTS * 9 * 256];
__device__ __align__(16) float g_b1eff[PPARTS * 256];
__device__ __align__(16) float g_b3   [PPARTS * 32];

// ---------------------------------------------------------------------------
// prep kernels (layouts validated R12-R15)
// ---------------------------------------------------------------------------
__global__ void prep_small(const float* __restrict__ W1, const float* __restrict__ b1,
                           const float* __restrict__ b3, const float* __restrict__ bocc,
                           const float* __restrict__ frame) {
    int p = blockIdx.x, d = threadIdx.x;
    const int rows[9] = {0, 1, 2, 11, 12, 13, 14, 15, 16};
    float be = b1[p * 256 + d];
#pragma unroll
    for (int f = 0; f < 8; ++f)
        be += frame[f] * W1[(p * 17 + 3 + f) * 256 + d];
    g_b1eff[p * 256 + d] = be;
#pragma unroll
    for (int i = 0; i < 9; ++i)
        g_W1r[(p * 9 + i) * 256 + d] = W1[(p * 17 + rows[i]) * 256 + d];
    if (d < 32) {
        float v = 0.f;
        if (d < 20)  v = b3[p * 20 + d];
        if (d == 20) v = bocc[p];
        g_b3[p * 32 + d] = v;
    }
}

// W2 fragments: PTX m16n8k16 B fragment, lane l (q=l%4, g=l/4):
//   regs = { B[k0+2q][n0+g], B[k0+2q+1][n0+g] }, { B[k0+8+2q], B[k0+9+2q] }
__global__ void prep_B2(const float* __restrict__ W2) {
    const int p = blockIdx.x, s = blockIdx.y, wx = blockIdx.z;
    const int tid = threadIdx.x;                 // 256
    const int ks2 = tid >> 7, t = (tid >> 5) & 3, lane = tid & 31;
    const int q = lane & 3, g = lane >> 2;
    const int hs = s * 2 + ks2;
    const int k0 = hs * 16;
    const int n0 = wx * 64 + t * 16;
    const float* Wp = W2 + (size_t)p * 256 * 256;

    auto h = [&](int k, int n) { return __float2half_rn(Wp[k * 256 + n]); };
    uint4 v;
    v.x = pack_hh(h(k0 + 2*q,     n0 + g),     h(k0 + 2*q + 1, n0 + g));
    v.y = pack_hh(h(k0 + 8 + 2*q, n0 + g),     h(k0 + 9 + 2*q, n0 + g));
    v.z = pack_hh(h(k0 + 2*q,     n0 + 8 + g), h(k0 + 2*q + 1, n0 + 8 + g));
    v.w = pack_hh(h(k0 + 8 + 2*q, n0 + 8 + g), h(k0 + 9 + 2*q, n0 + 8 + g));
    g_B2[(((size_t)(p * 4 + wx) * 16 + hs) * 4 + t) * 32 + lane] = v;
}

// W3 fragments: B3[k][r] = [W3|Wocc|0]^T, fp16 hi only (single-chain layer3)
__global__ void prep_B3(const float* __restrict__ W3,
                        const float* __restrict__ Wocc) {
    const int p = blockIdx.x, ks = blockIdx.y;
    const int tid = threadIdx.x;                 // 64
    const int nh = tid >> 5, lane = tid & 31;
    const int q = lane & 3, g = lane >> 2;
    const int k0 = ks * 16, n0 = nh * 16;

    auto hv = [&](int k, int r) {
        float w = 0.f;
        if (r < 20)  w = W3[((size_t)(p * 256 + k)) * 20 + r];
        if (r == 20) w = Wocc[(size_t)p * 256 + k];
        return __float2half_rn(w);
    };
    uint4 v;
    v.x = pack_hh(hv(k0 + 2*q,     n0 + g),     hv(k0 + 2*q + 1, n0 + g));
    v.y = pack_hh(hv(k0 + 8 + 2*q, n0 + g),     hv(k0 + 9 + 2*q, n0 + g));
    v.z = pack_hh(hv(k0 + 2*q,     n0 + 8 + g), hv(k0 + 2*q + 1, n0 + 8 + g));
    v.w = pack_hh(hv(k0 + 8 + 2*q, n0 + 8 + g), hv(k0 + 9 + 2*q, n0 + 8 + g));
    g_B3[(((size_t)(p * 2 + nh)) * 16 + ks) * 32 + lane] = v;
}

// ---------------------------------------------------------------------------
// main fused kernel
// ---------------------------------------------------------------------------
__global__ void __launch_bounds__(THREADS, 2)
fused_kernel(const float* __restrict__ tpts,
             const float* __restrict__ bigpts,
             const float* __restrict__ viewdir,
             const float* __restrict__ b2g,
             const int* __restrict__ tflag,
             float* __restrict__ out) {
    extern __shared__ unsigned char smc[];
    const int tid  = threadIdx.x;
    const int lane = tid & 31;
    const int wid  = tid >> 5;
    const int wy   = wid >> 2;          // layer2: m tile of 32
    const int wx   = wid & 3;           // layer2: n tile of 64
    const int n0   = blockIdx.x * TM;

    const unsigned sb = smem_to_u32(smc);

    // ---- layer2 A ldmatrix bases (validated R6-R15) ----
    unsigned a_rb[2], a_msk[2];
#pragma unroll
    for (int mt = 0; mt < 2; ++mt) {
        int ml = wy * 32 + mt * 16 + (lane & 15);
        a_rb[mt]  = (unsigned)(ml * 512 + (lane >> 4) * 16);
        a_msk[mt] = (unsigned)((ml & 7) << 4);
    }
    // ---- layer3 bases: warp w -> m-tile (w>>1), n-half (w&1) ----
    const int ml3 = (wid >> 1) * 16 + (lane & 15);
    const unsigned a3_rb  = (unsigned)(ml3 * 512 + (lane >> 4) * 16);
    const unsigned a3_msk = (unsigned)((ml3 & 7) << 4);
    const int nh = wid & 1;
    const int r0 = (wid >> 1) * 16 + (lane >> 2);
    const int r1 = r0 + 8;
    const int cbase = nh * 16 + (lane & 3) * 2;

    float sums[2][4];
#pragma unroll
    for (int t = 0; t < 2; ++t)
#pragma unroll
        for (int q = 0; q < 4; ++q) sums[t][q] = 0.f;

    for (int p = 0; p < PPARTS; ++p) {
        const uint4* bbase = g_B2 + (size_t)(p * 4 + wx) * 2048 + lane;

        // prefetch first half-stage's B fragments (hides behind layer1+bar)
        uint4 b0[4], b1[4];
#pragma unroll
        for (int t = 0; t < 4; ++t) b0[t] = __ldg(bbase + t * 32);

        // ---------------- layer 1 (thread = (m, d-chunk of 64)) ----------
        {
            const int m1 = tid & 63;
            const int dc = tid >> 6;
            const int gi = (n0 + m1) * PPARTS + p;
            float x[9];
            x[0] = tpts[gi*3];    x[1] = tpts[gi*3+1];    x[2] = tpts[gi*3+2];
            x[3] = bigpts[gi*3];  x[4] = bigpts[gi*3+1];  x[5] = bigpts[gi*3+2];
            x[6] = viewdir[gi*3]; x[7] = viewdir[gi*3+1]; x[8] = viewdir[gi*3+2];
            const float* w1  = g_W1r + p * 2304;
            const float* b1e = g_b1eff + p * 256;
            const unsigned amask = (unsigned)((m1 & 7) << 4);
            const unsigned mrow  = (unsigned)(m1 * 512 + dc * 128);
#pragma unroll 4
            for (int gq = 0; gq < 16; ++gq) {
                const int d = dc * 64 + gq * 4;
                float4 a = *(const float4*)(b1e + d);
#pragma unroll
                for (int i = 0; i < 9; ++i) {
                    float4 w = *(const float4*)(w1 + i * 256 + d);
                    a.x += x[i]*w.x; a.y += x[i]*w.y;
                    a.z += x[i]*w.z; a.w += x[i]*w.w;
                }
                a.x = fmaxf(a.x, 0.f); a.y = fmaxf(a.y, 0.f);
                a.z = fmaxf(a.z, 0.f); a.w = fmaxf(a.w, 0.f);
                unsigned o0 = (mrow + gq * 8) ^ amask;
                unsigned o1 = (mrow + gq * 8 + 4) ^ amask;
                *(unsigned*)(smc + OFF_AHI + o0) = pack_h2(a.x, a.y);
                *(unsigned*)(smc + OFF_AHI + o1) = pack_h2(a.z, a.w);
            }
        }
        __syncthreads();   // (1) A plane ready CTA-wide

        // ---------------- layer 2: A+B double-buffered, barrier-free -----
        float acc[2][8][4];
#pragma unroll
        for (int mt = 0; mt < 2; ++mt)
#pragma unroll
            for (int nt = 0; nt < 8; ++nt)
#pragma unroll
                for (int q = 0; q < 4; ++q) acc[mt][nt][q] = 0.f;

        unsigned ah0[2][4], ah1[2][4];
        // prologue: A fragments for half-stage 0
        LDSM4(ah0[0], sb + OFF_AHI + (a_rb[0] ^ a_msk[0]));
        LDSM4(ah0[1], sb + OFF_AHI + (a_rb[1] ^ a_msk[1]));

#pragma unroll 1
        for (int hs = 0; hs < 16; hs += 2) {
            // B for hs+1 in flight
#pragma unroll
            for (int t = 0; t < 4; ++t)
                b1[t] = __ldg(bbase + (hs + 1) * 128 + t * 32);
            // A for hs+1 in flight (before consuming hs)
            {
                const unsigned cc = (unsigned)(hs * 32 + 32);
                LDSM4(ah1[0], sb + OFF_AHI + ((a_rb[0] + cc) ^ a_msk[0]));
                LDSM4(ah1[1], sb + OFF_AHI + ((a_rb[1] + cc) ^ a_msk[1]));
            }
            // MMAs for hs (ah0 / b0)
#pragma unroll
            for (int mt = 0; mt < 2; ++mt)
#pragma unroll
                for (int t = 0; t < 4; ++t) {
                    MMA16816(acc[mt][2*t],   ah0[mt], b0[t].x, b0[t].y);
                    MMA16816(acc[mt][2*t+1], ah0[mt], b0[t].z, b0[t].w);
                }
            // B for hs+2 in flight
            if (hs + 2 < 16) {
#pragma unroll
                for (int t = 0; t < 4; ++t)
                    b0[t] = __ldg(bbase + (hs + 2) * 128 + t * 32);
                // A for hs+2 in flight (before consuming hs+1)
                const unsigned cc = (unsigned)(hs * 32 + 64);
                LDSM4(ah0[0], sb + OFF_AHI + ((a_rb[0] + cc) ^ a_msk[0]));
                LDSM4(ah0[1], sb + OFF_AHI + ((a_rb[1] + cc) ^ a_msk[1]));
            }
            // MMAs for hs+1 (ah1 / b1)
#pragma unroll
            for (int mt = 0; mt < 2; ++mt)
#pragma unroll
                for (int t = 0; t < 4; ++t) {
                    MMA16816(acc[mt][2*t],   ah1[mt], b1[t].x, b1[t].y);
                    MMA16816(acc[mt][2*t+1], ah1[mt], b1[t].z, b1[t].w);
                }
        }
        // no barrier: epilogue writes OFF_H2, disjoint from OFF_AHI reads

        // ---------------- epilogue: acc -> h2 fp16 plane (hi only) -------
#pragma unroll
        for (int mt = 0; mt < 2; ++mt) {
            const int row0 = wy * 32 + mt * 16 + (lane >> 2);
#pragma unroll
            for (int nt = 0; nt < 8; ++nt) {
                const int e = wx * 64 + nt * 8 + (lane & 3) * 2;
                float2 bv = *(const float2*)(b2g + p * 256 + e);
                float v0 = fmaxf(acc[mt][nt][0] + bv.x, 0.f);
                float v1 = fmaxf(acc[mt][nt][1] + bv.y, 0.f);
                float v2 = fmaxf(acc[mt][nt][2] + bv.x, 0.f);
                float v3 = fmaxf(acc[mt][nt][3] + bv.y, 0.f);
                unsigned o0 = (unsigned)(row0 * 512 + e * 2) ^
                              (unsigned)((row0 & 7) << 4);
                unsigned o1 = (unsigned)((row0 + 8) * 512 + e * 2) ^
                              (unsigned)(((row0 + 8) & 7) << 4);
                *(unsigned*)(smc + OFF_H2 + o0) = pack_h2(v0, v1);
                *(unsigned*)(smc + OFF_H2 + o1) = pack_h2(v2, v3);
            }
        }
        __syncthreads();   // (2) h2 plane visible CTA-wide
                           //     (also: all layer2 A reads done)

        // ---------------- layer 3: single chain, pipelined B -------------
        float acc3[2][4];
#pragma unroll
        for (int t = 0; t < 2; ++t)
#pragma unroll
            for (int q = 0; q < 4; ++q) acc3[t][q] = 0.f;
        {
            const uint4* bhi = g_B3 + (size_t)(p * 2 + nh) * 512 + lane;
            uint4 bh = __ldg(bhi);
#pragma unroll 1
            for (int ks = 0; ks < 16; ++ks) {
                uint4 bhc = bh;
                if (ks + 1 < 16) bh = __ldg(bhi + (ks + 1) * 32);
                const unsigned cc = (unsigned)(ks * 32);
                unsigned ah[4];
                LDSM4(ah, sb + OFF_H2 + ((a3_rb + cc) ^ a3_msk));
                MMA16816(acc3[0], ah, bhc.x, bhc.y);
                MMA16816(acc3[1], ah, bhc.z, bhc.w);
            }
        }

        // ---------------- extraction: mask, sigmoid, accumulate ----------
        {
            const float fl0 = (tflag[(n0 + r0) * PPARTS + p] != 0) ? 1.f : 0.f;
            const float fl1 = (tflag[(n0 + r1) * PPARTS + p] != 0) ? 1.f : 0.f;
#pragma unroll
            for (int t = 0; t < 2; ++t) {
                const int c = cbase + t * 8;
                const float b3a = g_b3[p * 32 + c];
                const float b3b = g_b3[p * 32 + c + 1];
                float v0 = acc3[t][0] + b3a, v1 = acc3[t][1] + b3b;
                float v2 = acc3[t][2] + b3a, v3 = acc3[t][3] + b3b;
                if (c == 20) {
                    v0 = (1.f / (1.f + __expf(-v0))) * fl0;
                    v2 = (1.f / (1.f + __expf(-v2))) * fl1;
                    out[(size_t)(n0 + r0) * OUTC + 21 + p] = v0;   // tocc
                    out[(size_t)(n0 + r1) * OUTC + 21 + p] = v2;
                } else {
                    v0 *= fl0; v2 *= fl1;
                }
                v1 *= fl0; v3 *= fl1;
                sums[t][0] += v0; sums[t][1] += v1;
                sums[t][2] += v2; sums[t][3] += v3;
            }
        }
        __syncthreads();   // (3) layer3 h2 reads done; A plane free for next p
    }

    // ---------------- final masked means ----------------
    const float inv6 = 1.f / 6.f;
#pragma unroll
    for (int t = 0; t < 2; ++t) {
        const int c = cbase + t * 8;
        if (c < 21) {
            out[(size_t)(n0 + r0) * OUTC + c] = sums[t][0] * inv6;
            out[(size_t)(n0 + r1) * OUTC + c] = sums[t][2] * inv6;
        }
        if (c + 1 < 21) {
            out[(size_t)(n0 + r0) * OUTC + c + 1] = sums[t][1] * inv6;
            out[(size_t)(n0 + r1) * OUTC + c + 1] = sums[t][3] * inv6;
        }
    }
}

// ---------------------------------------------------------------------------
// launch
// ---------------------------------------------------------------------------
extern "C" void kernel_launch(void* const* d_in, const int* in_sizes, int n_in,
                              void* d_out, int out_size) {
    const float* tpts    = (const float*)d_in[0];
    const float* bigpts  = (const float*)d_in[1];
    const float* viewdir = (const float*)d_in[2];
    // d_in[3]=dists, d_in[4]=part_dist unused
    const float* frame   = (const float*)d_in[5];
    const float* W1      = (const float*)d_in[6];
    const float* b1      = (const float*)d_in[7];
    const float* W2      = (const float*)d_in[8];
    const float* b2      = (const float*)d_in[9];
    const float* W3      = (const float*)d_in[10];
    const float* b3      = (const float*)d_in[11];
    const float* Wocc    = (const float*)d_in[12];
    const float* bocc    = (const float*)d_in[13];
    const int*   tflag   = (const int*)d_in[14];
    float* out = (float*)d_out;

    prep_small<<<PPARTS, 256>>>(W1, b1, b3, bocc, frame);
    prep_B2<<<dim3(PPARTS, 8, 4), 256>>>(W2);
    prep_B3<<<dim3(PPARTS, 16), 64>>>(W3, Wocc);

    cudaFuncSetAttribute(fused_kernel,
                         cudaFuncAttributeMaxDynamicSharedMemorySize,
                         SMEM_BYTES);
    fused_kernel<<<NCTAS, THREADS, SMEM_BYTES>>>(tpts, bigpts, viewdir,
                                                 b2, tflag, out);
}

// round 17
// speedup vs baseline: 1.3282x; 1.3282x over previous
#include <cuda_runtime.h>
#include <cuda_fp16.h>

// ---------------------------------------------------------------------------
// TPoseHuman fused 6-part MLP — layers 2 AND 3 on tensor cores, fp16.
// R17 = R14 layer1/layer2 (validated, 356µs config) + NEW layer3:
//   D-fragment-as-A-fragment: layer2 accumulators are relu'd + packed in
//   registers and fed straight into mma.m16n8k8 against k8 B-fragments of W3.
//   No h2 smem plane, no h2 LDSM. Per-warp k64 partials are reduced across
//   the 4 wx-warps via small padded smem buffers. 2 CTA barriers per part.
// ---------------------------------------------------------------------------

#define NPTS    65536
#define PPARTS  6
#define TM      64
#define NCTAS   (NPTS / TM)       // 1024
#define THREADS 256
#define OUTC    27

// ---- smem byte offsets ----
#define OFF_AHI  0u               // 64 rows x 512B : layer1 A-hi plane (32KB)
#define OFF_BUF  32768u           // 8 warps x 32x36 fp32 partials (36864B)
#define BUF_PITCH 36              // floats per row (pad vs 32 for banks)
#define BUF_WARP  1152            // 32*36 floats per warp
#define SMEM_BYTES 69632

// ---------------------------------------------------------------------------
// asm helpers (baseline PTX, sm_80-era: family-safe on compute_103)
// ---------------------------------------------------------------------------
__device__ __forceinline__ unsigned smem_to_u32(const void* p) {
    unsigned a;
    asm("{ .reg .u64 t; cvta.to.shared.u64 t, %1; cvt.u32.u64 %0, t; }"
        : "=r"(a) : "l"(p));
    return a;
}
#define LDSM4(r, addr) \
    asm volatile("ldmatrix.sync.aligned.m8n8.x4.shared.b16 {%0,%1,%2,%3}, [%4];" \
        : "=r"((r)[0]), "=r"((r)[1]), "=r"((r)[2]), "=r"((r)[3]) : "r"(addr))
#define MMA16816(d, a, b0r, b1r) \
    asm volatile("mma.sync.aligned.m16n8k16.row.col.f32.f16.f16.f32 " \
        "{%0,%1,%2,%3}, {%4,%5,%6,%7}, {%8,%9}, {%0,%1,%2,%3};" \
        : "+f"((d)[0]), "+f"((d)[1]), "+f"((d)[2]), "+f"((d)[3]) \
        : "r"((a)[0]), "r"((a)[1]), "r"((a)[2]), "r"((a)[3]), \
          "r"(b0r), "r"(b1r))
#define MMA16808(d, a0r, a1r, br) \
    asm volatile("mma.sync.aligned.m16n8k8.row.col.f32.f16.f16.f32 " \
        "{%0,%1,%2,%3}, {%4,%5}, {%6}, {%0,%1,%2,%3};" \
        : "+f"((d)[0]), "+f"((d)[1]), "+f"((d)[2]), "+f"((d)[3]) \
        : "r"(a0r), "r"(a1r), "r"(br))
__device__ __forceinline__ unsigned pack_h2(float x, float y) {
    __half2 t = __floats2half2_rn(x, y);
    return *(unsigned*)&t;
}
__device__ __forceinline__ unsigned pack_hh(__half x, __half y) {
    __half2 t = __halves2half2(x, y);
    return *(unsigned*)&t;
}

// ---------------------------------------------------------------------------
// persistent scratch — B operands in direct MMA-fragment layout
// ---------------------------------------------------------------------------
// g_B2: [p][wx(4)][hs(16)][t(4)][lane(32)] x uint4 (validated R12-R16)
__device__ __align__(16) uint4 g_B2[PPARTS * 4 * 16 * 4 * 32];      // 786KB
// g_B3: [p][c(32 k8-chunks)][lane(32)] x uint4 = {rt0,rt1,rt2,rt3} k8 B-frags
__device__ __align__(16) uint4 g_B3[PPARTS * 32 * 32];              // 98KB
__device__ __align__(16) float g_W1r  [PPARTS * 9 * 256];
__device__ __align__(16) float g_b1eff[PPARTS * 256];
__device__ __align__(16) float g_b3   [PPARTS * 32];

// ---------------------------------------------------------------------------
// prep kernels
// ---------------------------------------------------------------------------
__global__ void prep_small(const float* __restrict__ W1, const float* __restrict__ b1,
                           const float* __restrict__ b3, const float* __restrict__ bocc,
                           const float* __restrict__ frame) {
    int p = blockIdx.x, d = threadIdx.x;
    const int rows[9] = {0, 1, 2, 11, 12, 13, 14, 15, 16};
    float be = b1[p * 256 + d];
#pragma unroll
    for (int f = 0; f < 8; ++f)
        be += frame[f] * W1[(p * 17 + 3 + f) * 256 + d];
    g_b1eff[p * 256 + d] = be;
#pragma unroll
    for (int i = 0; i < 9; ++i)
        g_W1r[(p * 9 + i) * 256 + d] = W1[(p * 17 + rows[i]) * 256 + d];
    if (d < 32) {
        float v = 0.f;
        if (d < 20)  v = b3[p * 20 + d];
        if (d == 20) v = bocc[p];
        g_b3[p * 32 + d] = v;
    }
}

// W2 fragments: PTX m16n8k16 B fragment (validated R12-R16).
__global__ void prep_B2(const float* __restrict__ W2) {
    const int p = blockIdx.x, s = blockIdx.y, wx = blockIdx.z;
    const int tid = threadIdx.x;                 // 256
    const int ks2 = tid >> 7, t = (tid >> 5) & 3, lane = tid & 31;
    const int q = lane & 3, g = lane >> 2;
    const int hs = s * 2 + ks2;
    const int k0 = hs * 16;
    const int n0 = wx * 64 + t * 16;
    const float* Wp = W2 + (size_t)p * 256 * 256;

    auto h = [&](int k, int n) { return __float2half_rn(Wp[k * 256 + n]); };
    uint4 v;
    v.x = pack_hh(h(k0 + 2*q,     n0 + g),     h(k0 + 2*q + 1, n0 + g));
    v.y = pack_hh(h(k0 + 8 + 2*q, n0 + g),     h(k0 + 9 + 2*q, n0 + g));
    v.z = pack_hh(h(k0 + 2*q,     n0 + 8 + g), h(k0 + 2*q + 1, n0 + 8 + g));
    v.w = pack_hh(h(k0 + 8 + 2*q, n0 + 8 + g), h(k0 + 9 + 2*q, n0 + 8 + g));
    g_B2[(((size_t)(p * 4 + wx) * 16 + hs) * 4 + t) * 32 + lane] = v;
}

// W3 k8 B-fragments: for k8 chunk c, lane l (q=l%4, g=l/4), r-tile rt:
//   reg = { B3[c*8+2q][rt*8+g], B3[c*8+2q+1][rt*8+g] }   (B3[k][r]=[W3|Wocc|0])
__global__ void prep_B3(const float* __restrict__ W3,
                        const float* __restrict__ Wocc) {
    const int p = blockIdx.x, c = blockIdx.y;    // c = 0..31
    const int lane = threadIdx.x;                // 32
    const int q = lane & 3, g = lane >> 2;

    auto hv = [&](int k, int r) {
        float w = 0.f;
        if (r < 20)  w = W3[((size_t)(p * 256 + k)) * 20 + r];
        if (r == 20) w = Wocc[(size_t)p * 256 + k];
        return __float2half_rn(w);
    };
    const int k0 = c * 8;
    uint4 v;
    v.x = pack_hh(hv(k0 + 2*q,  0 + g), hv(k0 + 2*q + 1,  0 + g));
    v.y = pack_hh(hv(k0 + 2*q,  8 + g), hv(k0 + 2*q + 1,  8 + g));
    v.z = pack_hh(hv(k0 + 2*q, 16 + g), hv(k0 + 2*q + 1, 16 + g));
    v.w = pack_hh(hv(k0 + 2*q, 24 + g), hv(k0 + 2*q + 1, 24 + g));
    g_B3[((size_t)p * 32 + c) * 32 + lane] = v;
}

// ---------------------------------------------------------------------------
// main fused kernel
// ---------------------------------------------------------------------------
__global__ void __launch_bounds__(THREADS, 2)
fused_kernel(const float* __restrict__ tpts,
             const float* __restrict__ bigpts,
             const float* __restrict__ viewdir,
             const float* __restrict__ b2g,
             const int* __restrict__ tflag,
             float* __restrict__ out) {
    extern __shared__ unsigned char smc[];
    const int tid  = threadIdx.x;
    const int lane = tid & 31;
    const int wid  = tid >> 5;
    const int wy   = wid >> 2;          // layer2: m tile of 32
    const int wx   = wid & 3;           // layer2: n tile of 64
    const int n0   = blockIdx.x * TM;

    const unsigned sb = smem_to_u32(smc);

    // ---- layer2 A ldmatrix bases (validated R6-R16) ----
    unsigned a_rb[2], a_msk[2];
#pragma unroll
    for (int mt = 0; mt < 2; ++mt) {
        int ml = wy * 32 + mt * 16 + (lane & 15);
        a_rb[mt]  = (unsigned)(ml * 512 + (lane >> 4) * 16);
        a_msk[mt] = (unsigned)((ml & 7) << 4);
    }

    // ---- extraction mapping: thread = (row m, r-group of 8) ----
    const int em = tid >> 2;            // 0..63
    const int rg = tid & 3;             // cols rg*8 .. rg*8+7
    float sums[8];
#pragma unroll
    for (int j = 0; j < 8; ++j) sums[j] = 0.f;

    for (int p = 0; p < PPARTS; ++p) {
        const uint4* bbase = g_B2 + (size_t)(p * 4 + wx) * 2048 + lane;

        // prefetch first half-stage's B fragments (hides behind layer1+bar)
        uint4 b0[4], b1[4];
#pragma unroll
        for (int t = 0; t < 4; ++t) b0[t] = __ldg(bbase + t * 32);

        // ---------------- layer 1 (thread = (m, d-chunk of 64)) ----------
        {
            const int m1 = tid & 63;
            const int dc = tid >> 6;
            const int gi = (n0 + m1) * PPARTS + p;
            float x[9];
            x[0] = tpts[gi*3];    x[1] = tpts[gi*3+1];    x[2] = tpts[gi*3+2];
            x[3] = bigpts[gi*3];  x[4] = bigpts[gi*3+1];  x[5] = bigpts[gi*3+2];
            x[6] = viewdir[gi*3]; x[7] = viewdir[gi*3+1]; x[8] = viewdir[gi*3+2];
            const float* w1  = g_W1r + p * 2304;
            const float* b1e = g_b1eff + p * 256;
            const unsigned amask = (unsigned)((m1 & 7) << 4);
            const unsigned mrow  = (unsigned)(m1 * 512 + dc * 128);
#pragma unroll 4
            for (int gq = 0; gq < 16; ++gq) {
                const int d = dc * 64 + gq * 4;
                float4 a = *(const float4*)(b1e + d);
#pragma unroll
                for (int i = 0; i < 9; ++i) {
                    float4 w = *(const float4*)(w1 + i * 256 + d);
                    a.x += x[i]*w.x; a.y += x[i]*w.y;
                    a.z += x[i]*w.z; a.w += x[i]*w.w;
                }
                a.x = fmaxf(a.x, 0.f); a.y = fmaxf(a.y, 0.f);
                a.z = fmaxf(a.z, 0.f); a.w = fmaxf(a.w, 0.f);
                unsigned o0 = (mrow + gq * 8) ^ amask;
                unsigned o1 = (mrow + gq * 8 + 4) ^ amask;
                *(unsigned*)(smc + OFF_AHI + o0) = pack_h2(a.x, a.y);
                *(unsigned*)(smc + OFF_AHI + o1) = pack_h2(a.z, a.w);
            }
        }
        __syncthreads();   // (1) A plane ready CTA-wide; also orders prev
                           //     part's buffer reads before this part's stores

        // ---------------- layer 2: reg-pipelined B (R14 form) ------------
        float acc[2][8][4];
#pragma unroll
        for (int mt = 0; mt < 2; ++mt)
#pragma unroll
            for (int nt = 0; nt < 8; ++nt)
#pragma unroll
                for (int q = 0; q < 4; ++q) acc[mt][nt][q] = 0.f;

#pragma unroll 1
        for (int hs = 0; hs < 16; hs += 2) {
#pragma unroll
            for (int t = 0; t < 4; ++t)
                b1[t] = __ldg(bbase + (hs + 1) * 128 + t * 32);
            {
                const unsigned cc = (unsigned)(hs * 32);
                unsigned ah[2][4];
                LDSM4(ah[0], sb + OFF_AHI + ((a_rb[0] + cc) ^ a_msk[0]));
                LDSM4(ah[1], sb + OFF_AHI + ((a_rb[1] + cc) ^ a_msk[1]));
#pragma unroll
                for (int mt = 0; mt < 2; ++mt)
#pragma unroll
                    for (int t = 0; t < 4; ++t) {
                        MMA16816(acc[mt][2*t],   ah[mt], b0[t].x, b0[t].y);
                        MMA16816(acc[mt][2*t+1], ah[mt], b0[t].z, b0[t].w);
                    }
            }
            if (hs + 2 < 16) {
#pragma unroll
                for (int t = 0; t < 4; ++t)
                    b0[t] = __ldg(bbase + (hs + 2) * 128 + t * 32);
            }
            {
                const unsigned cc = (unsigned)(hs * 32 + 32);
                unsigned ah[2][4];
                LDSM4(ah[0], sb + OFF_AHI + ((a_rb[0] + cc) ^ a_msk[0]));
                LDSM4(ah[1], sb + OFF_AHI + ((a_rb[1] + cc) ^ a_msk[1]));
#pragma unroll
                for (int mt = 0; mt < 2; ++mt)
#pragma unroll
                    for (int t = 0; t < 4; ++t) {
                        MMA16816(acc[mt][2*t],   ah[mt], b1[t].x, b1[t].y);
                        MMA16816(acc[mt][2*t+1], ah[mt], b1[t].z, b1[t].w);
                    }
            }
        }

        // ---------------- layer 3 in registers: D-frag -> A-frag ---------
        // relu(acc + b2) packed to fp16 m16k8 A fragments; W3 as k8 B frags.
        float acc3[2][4][4];
#pragma unroll
        for (int mt = 0; mt < 2; ++mt)
#pragma unroll
            for (int rt = 0; rt < 4; ++rt)
#pragma unroll
                for (int q = 0; q < 4; ++q) acc3[mt][rt][q] = 0.f;
        {
            const uint4* b3p = g_B3 + ((size_t)p * 32 + wx * 8) * 32 + lane;
            uint4 bb = __ldg(b3p);
#pragma unroll
            for (int nt = 0; nt < 8; ++nt) {
                uint4 bc = bb;
                if (nt + 1 < 8) bb = __ldg(b3p + (nt + 1) * 32);
                float2 bv = *(const float2*)(b2g + p * 256 + wx * 64 +
                                             nt * 8 + (lane & 3) * 2);
#pragma unroll
                for (int mt = 0; mt < 2; ++mt) {
                    unsigned a0 = pack_h2(fmaxf(acc[mt][nt][0] + bv.x, 0.f),
                                          fmaxf(acc[mt][nt][1] + bv.y, 0.f));
                    unsigned a1 = pack_h2(fmaxf(acc[mt][nt][2] + bv.x, 0.f),
                                          fmaxf(acc[mt][nt][3] + bv.y, 0.f));
                    MMA16808(acc3[mt][0], a0, a1, bc.x);
                    MMA16808(acc3[mt][1], a0, a1, bc.y);
                    MMA16808(acc3[mt][2], a0, a1, bc.z);
                    MMA16808(acc3[mt][3], a0, a1, bc.w);
                }
            }
        }

        // ---------------- store per-warp k64 partials to smem ------------
        {
            float* buf = (float*)(smc + OFF_BUF) + wid * BUF_WARP;
#pragma unroll
            for (int mt = 0; mt < 2; ++mt) {
                const int row0 = mt * 16 + (lane >> 2);
#pragma unroll
                for (int rt = 0; rt < 4; ++rt) {
                    const int col = rt * 8 + (lane & 3) * 2;
                    *(float2*)(buf + row0 * BUF_PITCH + col) =
                        make_float2(acc3[mt][rt][0], acc3[mt][rt][1]);
                    *(float2*)(buf + (row0 + 8) * BUF_PITCH + col) =
                        make_float2(acc3[mt][rt][2], acc3[mt][rt][3]);
                }
            }
        }
        __syncthreads();   // (2) partials visible; layer2 A reads done

        // ---------------- extraction: reduce 4 wx partials ---------------
        {
            const int lm = em & 31;
            const int wb = (em >> 5) * 4;      // buffer group (wy)
            float4 s0 = make_float4(0.f, 0.f, 0.f, 0.f);
            float4 s1 = make_float4(0.f, 0.f, 0.f, 0.f);
#pragma unroll
            for (int w = 0; w < 4; ++w) {
                const float* b = (const float*)(smc + OFF_BUF) +
                                 (wb + w) * BUF_WARP + lm * BUF_PITCH + rg * 8;
                float4 x0 = *(const float4*)(b);
                float4 x1 = *(const float4*)(b + 4);
                s0.x += x0.x; s0.y += x0.y; s0.z += x0.z; s0.w += x0.w;
                s1.x += x1.x; s1.y += x1.y; s1.z += x1.z; s1.w += x1.w;
            }
            float sv[8] = {s0.x, s0.y, s0.z, s0.w, s1.x, s1.y, s1.z, s1.w};
            const float flag = (tflag[(n0 + em) * PPARTS + p] != 0) ? 1.f : 0.f;
#pragma unroll
            for (int j = 0; j < 8; ++j) {
                const int c = rg * 8 + j;
                if (c < 21) {
                    float v = sv[j] + g_b3[p * 32 + c];
                    if (c == 20) {
                        v = 1.f / (1.f + __expf(-v));
                        v *= flag;
                        out[(size_t)(n0 + em) * OUTC + 21 + p] = v;  // tocc
                    } else {
                        v *= flag;
                    }
                    sums[j] += v;
                }
            }
        }
        // no third barrier: next layer1 writes A plane (disjoint from BUF);
        // BUF WAR is ordered by next barrier (1).
    }

    // ---------------- final masked means ----------------
    const float inv6 = 1.f / 6.f;
#pragma unroll
    for (int j = 0; j < 8; ++j) {
        const int c = rg * 8 + j;
        if (c < 21)
            out[(size_t)(n0 + em) * OUTC + c] = sums[j] * inv6;
    }
}

// ---------------------------------------------------------------------------
// launch
// ---------------------------------------------------------------------------
extern "C" void kernel_launch(void* const* d_in, const int* in_sizes, int n_in,
                              void* d_out, int out_size) {
    const float* tpts    = (const float*)d_in[0];
    const float* bigpts  = (const float*)d_in[1];
    const float* viewdir = (const float*)d_in[2];
    // d_in[3]=dists, d_in[4]=part_dist unused
    const float* frame   = (const float*)d_in[5];
    const float* W1      = (const float*)d_in[6];
    const float* b1      = (const float*)d_in[7];
    const float* W2      = (const float*)d_in[8];
    const float* b2      = (const float*)d_in[9];
    const float* W3      = (const float*)d_in[10];
    const float* b3      = (const float*)d_in[11];
    const float* Wocc    = (const float*)d_in[12];
    const float* bocc    = (const float*)d_in[13];
    const int*   tflag   = (const int*)d_in[14];
    float* out = (float*)d_out;

    prep_small<<<PPARTS, 256>>>(W1, b1, b3, bocc, frame);
    prep_B2<<<dim3(PPARTS, 8, 4), 256>>>(W2);
    prep_B3<<<dim3(PPARTS, 32), 32>>>(W3, Wocc);

    cudaFuncSetAttribute(fused_kernel,
                         cudaFuncAttributeMaxDynamicSharedMemorySize,
                         SMEM_BYTES);
    fused_kernel<<<NCTAS, THREADS, SMEM_BYTES>>>(tpts, bigpts, viewdir,
                                                 b2, tflag, out);
}